// round 1
// baseline (speedup 1.0000x reference)
#include <cuda_runtime.h>
#include <cstdint>

namespace {
constexpr int B = 32, S = 1024, DM = 128, DI = 256, DS = 16, DTR = 8, NL = 4;
constexpr int MTOT = B * S;
}

// ---------------- scratch (device globals; no allocation allowed) -------------
__device__ float g_h[MTOT * DM];        // residual stream
__device__ float g_hn[MTOT * DM];       // rmsnormed
__device__ float g_xz[MTOT * 2 * DI];   // in_proj out: [xb | z]
__device__ float g_xc[MTOT * DI];       // conv+silu out (u)
__device__ float g_dbc[MTOT * 40];      // x_proj out: [dt_rank(8) | B(16) | C(16)]
__device__ float g_delta[MTOT * DI];
__device__ float g_y[MTOT * DI];
__device__ float g_g[MTOT * DI];        // gated y

__device__ __forceinline__ float siluf(float x) { return x / (1.f + __expf(-x)); }

// ---------------- GEMM: C[M,N] = A[M,K] @ W[N,K]^T (+bias / +=) ---------------
// BM=128, BK=16, TM=8. BN/TN templated. EPI: 0=store(+bias), 1=add into C.
template <int BN, int TN, int EPI>
__global__ void __launch_bounds__(256, 2) gemm_nt(
    const float* __restrict__ A, const float* __restrict__ W,
    const float* __restrict__ bias, float* __restrict__ C,
    int M, int N, int K)
{
    constexpr int BM = 128, BK = 16, TM = 8;
    __shared__ float As[BK][BM + 4];
    __shared__ float Ws[BK][BN + 4];
    const int tid = threadIdx.x;
    const int bm = blockIdx.y * BM;
    const int bn = blockIdx.x * BN;
    const int tx = tid & 15;
    const int ty = tid >> 4;
    const int lrow = tid >> 2;          // 0..63
    const int lk = (tid & 3) * 4;       // 0,4,8,12

    float acc[TM][TN];
#pragma unroll
    for (int i = 0; i < TM; i++)
#pragma unroll
        for (int j = 0; j < TN; j++) acc[i][j] = 0.f;

    const float* Ap0 = A + (size_t)(bm + lrow) * K + lk;
    const float* Ap1 = Ap0 + (size_t)64 * K;

    for (int k0 = 0; k0 < K; k0 += BK) {
        float4 a0 = *(const float4*)(Ap0 + k0);
        float4 a1 = *(const float4*)(Ap1 + k0);
        float4 w0 = make_float4(0.f, 0.f, 0.f, 0.f);
        float4 w1 = make_float4(0.f, 0.f, 0.f, 0.f);
        int n0 = bn + lrow;
        if (n0 < N) w0 = *(const float4*)(W + (size_t)n0 * K + k0 + lk);
        if (BN == 128) {
            int n1 = bn + 64 + lrow;
            if (n1 < N) w1 = *(const float4*)(W + (size_t)n1 * K + k0 + lk);
        }
        As[lk + 0][lrow] = a0.x; As[lk + 1][lrow] = a0.y;
        As[lk + 2][lrow] = a0.z; As[lk + 3][lrow] = a0.w;
        As[lk + 0][64 + lrow] = a1.x; As[lk + 1][64 + lrow] = a1.y;
        As[lk + 2][64 + lrow] = a1.z; As[lk + 3][64 + lrow] = a1.w;
        Ws[lk + 0][lrow] = w0.x; Ws[lk + 1][lrow] = w0.y;
        Ws[lk + 2][lrow] = w0.z; Ws[lk + 3][lrow] = w0.w;
        if (BN == 128) {
            Ws[lk + 0][64 + lrow] = w1.x; Ws[lk + 1][64 + lrow] = w1.y;
            Ws[lk + 2][64 + lrow] = w1.z; Ws[lk + 3][64 + lrow] = w1.w;
        }
        __syncthreads();
#pragma unroll
        for (int kk = 0; kk < BK; kk++) {
            float ra[TM], rb[TN];
            *(float4*)&ra[0] = *(const float4*)&As[kk][ty * TM];
            *(float4*)&ra[4] = *(const float4*)&As[kk][ty * TM + 4];
            *(float4*)&rb[0] = *(const float4*)&Ws[kk][tx * TN];
            if (TN == 8) *(float4*)&rb[4] = *(const float4*)&Ws[kk][tx * TN + 4];
#pragma unroll
            for (int i = 0; i < TM; i++)
#pragma unroll
                for (int j = 0; j < TN; j++) acc[i][j] = fmaf(ra[i], rb[j], acc[i][j]);
        }
        __syncthreads();
    }
#pragma unroll
    for (int i = 0; i < TM; i++) {
        int row = bm + ty * TM + i;
#pragma unroll
        for (int j = 0; j < TN; j++) {
            int col = bn + tx * TN + j;
            if (col < N) {
                size_t idx = (size_t)row * N + col;
                float v = acc[i][j];
                if (bias) v += bias[col];
                if (EPI == 1) C[idx] += v;
                else C[idx] = v;
            }
        }
    }
}

// ---------------- RMSNorm (one row per 128-thread block) ----------------------
__global__ void rmsnorm_kernel(const float* __restrict__ x, const float* __restrict__ w,
                               float* __restrict__ out)
{
    int m = blockIdx.x;
    int tid = threadIdx.x;  // 128
    float v = x[(size_t)m * DM + tid];
    float s = v * v;
#pragma unroll
    for (int o = 16; o; o >>= 1) s += __shfl_xor_sync(0xffffffffu, s, o);
    __shared__ float red[4];
    if ((tid & 31) == 0) red[tid >> 5] = s;
    __syncthreads();
    float tot = red[0] + red[1] + red[2] + red[3];
    out[(size_t)m * DM + tid] = v * rsqrtf(tot * (1.f / DM) + 1e-5f) * w[tid];
}

// ---------------- depthwise causal conv (k=4) + silu --------------------------
__global__ void conv_kernel(const float* __restrict__ xz, const float* __restrict__ cw,
                            const float* __restrict__ cb, float* __restrict__ out)
{
    int idx = blockIdx.x * blockDim.x + threadIdx.x;  // MTOT*DI
    int e = idx & (DI - 1);
    int m = idx >> 8;
    int s = m & (S - 1);
    const float* xp = xz + (size_t)m * (2 * DI) + e;
    float w0 = cw[e * 4 + 0], w1 = cw[e * 4 + 1], w2 = cw[e * 4 + 2], w3 = cw[e * 4 + 3];
    float acc = cb[e];
    acc = fmaf(w3, xp[0], acc);
    if (s >= 1) acc = fmaf(w2, xp[-(2 * DI)], acc);
    if (s >= 2) acc = fmaf(w1, xp[-2 * (2 * DI)], acc);
    if (s >= 3) acc = fmaf(w0, xp[-3 * (2 * DI)], acc);
    out[(size_t)m * DI + e] = siluf(acc);
}

// ---------------- dt_proj (K=8) + softplus ------------------------------------
__global__ void dtproj_kernel(const float* __restrict__ dbc, const float* __restrict__ dtw,
                              const float* __restrict__ dtb, float* __restrict__ delta)
{
    constexpr int ROWS = 16;
    int tid = threadIdx.x;  // 256 -> one output channel per thread
    int m0 = blockIdx.x * ROWS;
    float wr[DTR];
#pragma unroll
    for (int k = 0; k < DTR; k++) wr[k] = dtw[tid * DTR + k];
    float bias = dtb[tid];
    __shared__ float rv[ROWS][DTR];
    if (tid < ROWS * DTR)
        rv[tid >> 3][tid & 7] = dbc[(size_t)(m0 + (tid >> 3)) * 40 + (tid & 7)];
    __syncthreads();
#pragma unroll
    for (int r = 0; r < ROWS; r++) {
        float x = bias;
#pragma unroll
        for (int k = 0; k < DTR; k++) x = fmaf(wr[k], rv[r][k], x);
        float d = (x > 20.f) ? x : log1pf(__expf(x));
        delta[(size_t)(m0 + r) * DI + tid] = d;
    }
}

// ---------------- selective scan ----------------------------------------------
// block: 256 thr = 8 warps; half-warp (16 lanes = 16 states) per channel;
// block covers 16 channels of one batch. grid = (DI/16, B).
__global__ void __launch_bounds__(256) scan_kernel(
    const float* __restrict__ delta, const float* __restrict__ dbc,
    const float* __restrict__ u, const float* __restrict__ A_log,
    const float* __restrict__ Dp, float* __restrict__ y)
{
    int b = blockIdx.y;
    int egrp = blockIdx.x;
    int warp = threadIdx.x >> 5;
    int lane = threadIdx.x & 31;
    int half = lane >> 4;
    int n = lane & 15;
    int e = egrp * 16 + warp * 2 + half;
    // A = -exp(A_log); fold log2(e) so dA = exp2f(d * a2)
    float a2 = -__expf(A_log[e * DS + n]) * 1.4426950408889634f;
    float dcoef = Dp[e];
    size_t base = (size_t)b * S;
    const float* dptr = delta + base * DI + e;
    const float* uptr = u + base * DI + e;
    const float* bptr = dbc + base * 40 + 8 + n;  // B at +0, C at +16
    float* yptr = y + base * DI + e;
    float h = 0.f;
    for (int t = 0; t < S; t += 4) {
        float dv[4], uv[4], Bv[4], Cv[4];
#pragma unroll
        for (int j = 0; j < 4; j++) {
            dv[j] = dptr[j * DI];
            uv[j] = uptr[j * DI];
            Bv[j] = bptr[j * 40];
            Cv[j] = bptr[j * 40 + 16];
        }
#pragma unroll
        for (int j = 0; j < 4; j++) {
            float dA = exp2f(dv[j] * a2);
            h = fmaf(dA, h, dv[j] * Bv[j] * uv[j]);
            float p = h * Cv[j];
            p += __shfl_xor_sync(0xffffffffu, p, 1);
            p += __shfl_xor_sync(0xffffffffu, p, 2);
            p += __shfl_xor_sync(0xffffffffu, p, 4);
            p += __shfl_xor_sync(0xffffffffu, p, 8);
            if (n == 0) yptr[j * DI] = fmaf(dcoef, uv[j], p);
        }
        dptr += 4 * DI; uptr += 4 * DI; bptr += 4 * 40; yptr += 4 * DI;
    }
}

// ---------------- gate: g = y * silu(z) ----------------------------------------
__global__ void gate_kernel(const float* __restrict__ y, const float* __restrict__ xz,
                            float* __restrict__ g)
{
    int idx = blockIdx.x * blockDim.x + threadIdx.x;  // MTOT*DI
    int e = idx & (DI - 1);
    int m = idx >> 8;
    float z = xz[(size_t)m * (2 * DI) + DI + e];
    g[idx] = y[idx] * siluf(z);
}

// ---------------- final: rmsnorm(last token) @ cls ----------------------------
__global__ void final_kernel(const float* __restrict__ h, const float* __restrict__ w,
                             const float* __restrict__ clsw, const float* __restrict__ clsb,
                             float* __restrict__ out)
{
    int b = blockIdx.x;
    int tid = threadIdx.x;  // 128
    float v = h[((size_t)b * S + (S - 1)) * DM + tid];
    float s = v * v;
#pragma unroll
    for (int o = 16; o; o >>= 1) s += __shfl_xor_sync(0xffffffffu, s, o);
    __shared__ float red[4];
    __shared__ float sh[DM];
    if ((tid & 31) == 0) red[tid >> 5] = s;
    __syncthreads();
    float tot = red[0] + red[1] + red[2] + red[3];
    sh[tid] = v * rsqrtf(tot * (1.f / DM) + 1e-5f) * w[tid];
    __syncthreads();
    if (tid < 2) {
        float acc = clsb[tid];
        for (int d = 0; d < DM; d++) acc = fmaf(sh[d], clsw[tid * DM + d], acc);
        out[b * 2 + tid] = acc;
    }
}

// ---------------- launcher ----------------------------------------------------
extern "C" void kernel_launch(void* const* d_in, const int* in_sizes, int n_in,
                              void* d_out, int out_size)
{
    (void)in_sizes; (void)n_in; (void)out_size;
    const float* x    = (const float*)d_in[0];
    const float* ipw  = (const float*)d_in[1];
    const float* ipb  = (const float*)d_in[2];
    const float* inw  = (const float*)d_in[3];
    const float* cw   = (const float*)d_in[4];
    const float* cb   = (const float*)d_in[5];
    const float* xpw  = (const float*)d_in[6];
    const float* dtw  = (const float*)d_in[7];
    const float* dtb  = (const float*)d_in[8];
    const float* alog = (const float*)d_in[9];
    const float* dvec = (const float*)d_in[10];
    const float* opw  = (const float*)d_in[11];
    const float* nw   = (const float*)d_in[12];
    const float* nfw  = (const float*)d_in[13];
    const float* clw  = (const float*)d_in[14];
    const float* clb  = (const float*)d_in[15];
    float* out = (float*)d_out;

    float *ph, *phn, *pxz, *pxc, *pdbc, *pdelta, *py, *pg;
    cudaGetSymbolAddress((void**)&ph, g_h);
    cudaGetSymbolAddress((void**)&phn, g_hn);
    cudaGetSymbolAddress((void**)&pxz, g_xz);
    cudaGetSymbolAddress((void**)&pxc, g_xc);
    cudaGetSymbolAddress((void**)&pdbc, g_dbc);
    cudaGetSymbolAddress((void**)&pdelta, g_delta);
    cudaGetSymbolAddress((void**)&py, g_y);
    cudaGetSymbolAddress((void**)&pg, g_g);

    // input proj: (MTOT x 64) @ (128 x 64)^T + b -> g_h
    gemm_nt<128, 8, 0><<<dim3(1, MTOT / 128), 256>>>(x, ipw, ipb, ph, MTOT, DM, 64);

    for (int i = 0; i < NL; i++) {
        rmsnorm_kernel<<<MTOT, 128>>>(ph, nw + i * DM, phn);
        gemm_nt<128, 8, 0><<<dim3(4, MTOT / 128), 256>>>(
            phn, inw + (size_t)i * 2 * DI * DM, nullptr, pxz, MTOT, 2 * DI, DM);
        conv_kernel<<<MTOT * DI / 256, 256>>>(pxz, cw + i * DI * 4, cb + i * DI, pxc);
        gemm_nt<64, 4, 0><<<dim3(1, MTOT / 128), 256>>>(
            pxc, xpw + (size_t)i * 40 * DI, nullptr, pdbc, MTOT, 40, DI);
        dtproj_kernel<<<MTOT / 16, 256>>>(pdbc, dtw + i * DI * DTR, dtb + i * DI, pdelta);
        scan_kernel<<<dim3(DI / 16, B), 256>>>(pdelta, pdbc, pxc,
                                               alog + i * DI * DS, dvec + i * DI, py);
        gate_kernel<<<MTOT * DI / 256, 256>>>(py, pxz, pg);
        gemm_nt<128, 8, 1><<<dim3(1, MTOT / 128), 256>>>(
            pg, opw + (size_t)i * DM * DI, nullptr, ph, MTOT, DM, DI);
    }

    final_kernel<<<B, 128>>>(ph, nfw, clw, clb, out);
}